// round 10
// baseline (speedup 1.0000x reference)
#include <cuda_runtime.h>
#include <math.h>
#include <stdint.h>

#define BATCH 8
#define TOTAL 21824
#define DETS  100
#define IMGF  1024.0f
#define STH   0.2f
#define NMST  0.6f
#define MAXB  128    // per-class bucket capacity (mean ~41, 13-sigma safe)
#define BINN  4096   // quantization bins
#define BCAP  512    // boundary-bin capacity (expected ~16)
#define OCAP  1024   // out contention capacity (expected ~110)
#define SCAP  3328   // survivor capacity (max possible 3320)

// dynamic smem layout (bytes) for k_batch:
//   [0,      81920)  buckets: 80 * MAXB u64
//   [81920,  82240)  bcnt:    80 int
//   [82240, 188736)  REGION (phase-overlaid):
//                      select: hist 16384 | binkeys 4096
//                      nms:    32 warps * 3328 scratch
//                      out:    hist 16384 | cont 8192
//   [188736, 215360) survivors: SCAP u64
#define OFF_BUCKETS 0
#define OFF_BCNT    81920
#define OFF_REGION  82240
#define OFF_SUR     188736
#define BATCH_SMEM  215360

// ---------------- scratch (only d_keys is global now) ----------------
__device__ unsigned long long d_keys[BATCH * TOTAL];

__device__ __forceinline__ float sigf(float x) { return 1.0f / (1.0f + expf(-x)); }

__device__ __forceinline__ float key_score_hi(unsigned h) {
    unsigned uo = ~h;
    unsigned bits = (uo & 0x80000000u) ? (uo ^ 0x80000000u) : (~uo);
    return __uint_as_float(bits);
}
__device__ __forceinline__ float key_score(unsigned long long key) {
    return key_score_hi((unsigned)(key >> 32));
}
// monotone: higher score -> higher bin; masked (-1) -> bin 0
__device__ __forceinline__ int qbin(unsigned h) {
    float s = key_score_hi(h);
    return (s > 0.0f) ? min(BINN - 1, (int)(s * (float)BINN)) : 0;
}

// ---------------- K1: staged coalesced score + argmax -> 64-bit key ----------------
// key = (~orderable(score))<<32 | idx<<7 | label : ascending == (score desc, idx asc);
// keys globally distinct; matches jax.lax.top_k stable tie order.
__global__ __launch_bounds__(512) void k_score(const float* __restrict__ logits,
                                               const float* __restrict__ ctr) {
    __shared__ float4 s4[128 * 20];  // 40 KB
    int tid = threadIdx.x;
    const float4* g = reinterpret_cast<const float4*>(logits) + (size_t)blockIdx.x * (128 * 20);
#pragma unroll
    for (int i = 0; i < 5; i++) s4[i * 512 + tid] = __ldcs(&g[i * 512 + tid]);
    __syncthreads();

    int la = tid >> 2;   // local anchor 0..127
    int q  = tid & 3;    // quarter: cols 20q..20q+19
    const float4* rowq = s4 + la * 20 + q * 5;
    float best = -1e30f;
    int bi = 0;
#pragma unroll
    for (int i = 0; i < 5; i++) {  // strict > keeps first-max within lane
        float4 v = rowq[i];
        int cb = q * 20 + i * 4;
        if (v.x > best) { best = v.x; bi = cb + 0; }
        if (v.y > best) { best = v.y; bi = cb + 1; }
        if (v.z > best) { best = v.z; bi = cb + 2; }
        if (v.w > best) { best = v.w; bi = cb + 3; }
    }
#pragma unroll
    for (int o = 2; o >= 1; o >>= 1) {  // tie -> lower column (= first occurrence)
        float ov = __shfl_down_sync(0xFFFFFFFFu, best, o);
        int   oc = __shfl_down_sync(0xFFFFFFFFu, bi, o);
        if (ov > best || (ov == best && oc < bi)) { best = ov; bi = oc; }
    }
    if (q == 0) {
        int ga = blockIdx.x * 128 + la;   // BATCH*TOTAL % 128 == 0
        float s = sqrtf(sigf(best) * sigf(ctr[ga]));
        float sm = (s > STH) ? s : -1.0f;
        unsigned u = __float_as_uint(sm);
        u ^= (u & 0x80000000u) ? 0xFFFFFFFFu : 0x80000000u;
        int i_loc = ga % TOTAL;
        d_keys[ga] = ((unsigned long long)(~u) << 32) |
                     ((unsigned)(i_loc << 7) | (unsigned)bi);
    }
}

// ============ K2: one block per batch — select + NMS + top-100, all in SMEM ============
__global__ __launch_bounds__(1024, 1) void k_batch(const float* __restrict__ reg,
                                                   const float* __restrict__ anchors,
                                                   float* __restrict__ out) {
    extern __shared__ unsigned char sm[];
    unsigned long long* buckets = (unsigned long long*)(sm + OFF_BUCKETS);
    int* bcnt = (int*)(sm + OFF_BCNT);
    unsigned long long* survivors = (unsigned long long*)(sm + OFF_SUR);

    __shared__ int warpsum[32];
    __shared__ unsigned long long win[DETS];
    __shared__ int sh_Q, sh_kneed, sh_bc, sh_cc, sh_sur;

    int b = blockIdx.x, tid = threadIdx.x, lane = tid & 31, wid = tid >> 5;
    const unsigned long long* kp = d_keys + b * TOTAL;

    for (int i = tid; i < 80; i += 1024) bcnt[i] = 0;
    if (tid == 0) sh_sur = 0;
    __syncthreads();

    // ================= phase S: per-level exact top-k -> smem class buckets =========
    {
        unsigned* hist = (unsigned*)(sm + OFF_REGION);
        unsigned long long* binkeys = (unsigned long long*)(sm + OFF_REGION + BINN * 4);
        const int LOFF[5] = {0, 16384, 20480, 21504, 21760};
        const int LN[5]   = {16384, 4096, 1024, 256, 64};
        const int LK[5]   = {1000, 1000, 1000, 256, 64};

        for (int lvl = 0; lvl < 5; lvl++) {
            int off = LOFF[lvl], n = LN[lvl], k = LK[lvl];
            if (k >= n) {  // levels 3,4: everything selected
                for (int i = tid; i < n; i += 1024) {
                    unsigned long long key = kp[off + i];
                    int c = (int)(key & 127ULL);
                    int pos = atomicAdd(&bcnt[c], 1);
                    if (pos < MAXB) buckets[c * MAXB + pos] = key;
                }
                __syncthreads();
                continue;
            }

            for (int i = tid; i < BINN; i += 1024) hist[i] = 0;
            if (tid == 0) sh_bc = 0;
            __syncthreads();

            // sweep 1: histogram (plain spread smem atomics; no warp-sync in loop)
            for (int i = tid; i < n; i += 1024)
                atomicAdd(&hist[qbin((unsigned)(kp[off + i] >> 32))], 1u);
            __syncthreads();

            // descending-bin cumulative scan (4 bins/thread): boundary bin Q, kneed
            {
                int vv[4], mysum = 0;
#pragma unroll
                for (int j = 0; j < 4; j++) { vv[j] = hist[BINN - 1 - (tid * 4 + j)]; mysum += vv[j]; }
                int inc = mysum;
#pragma unroll
                for (int o = 1; o < 32; o <<= 1) { int t2 = __shfl_up_sync(0xFFFFFFFFu, inc, o); if (lane >= o) inc += t2; }
                if (lane == 31) warpsum[wid] = inc;
                __syncthreads();
                if (tid < 32) {
                    int w = warpsum[tid], s = w;
#pragma unroll
                    for (int o = 1; o < 32; o <<= 1) { int t2 = __shfl_up_sync(0xFFFFFFFFu, s, o); if (tid >= o) s += t2; }
                    warpsum[tid] = s - w;  // exclusive
                }
                __syncthreads();
                int c = warpsum[wid] + inc - mysum;
#pragma unroll
                for (int j = 0; j < 4; j++) {
                    if (c < k && c + vv[j] >= k) {
                        sh_Q = BINN - 1 - (tid * 4 + j);
                        sh_kneed = k - c;
                    }
                    c += vv[j];
                }
            }
            __syncthreads();
            int Q = sh_Q, kneed = sh_kneed;

            // sweep 2: push bins > Q; collect boundary bin
            for (int i = tid; i < n; i += 1024) {
                unsigned long long key = kp[off + i];
                int q = qbin((unsigned)(key >> 32));
                if (q > Q) {
                    int c = (int)(key & 127ULL);
                    int pos = atomicAdd(&bcnt[c], 1);
                    if (pos < MAXB) buckets[c * MAXB + pos] = key;
                } else if (q == Q) {
                    int p = atomicAdd(&sh_bc, 1);
                    if (p < BCAP) binkeys[p] = key;
                }
            }
            __syncthreads();
            int C = min(sh_bc, BCAP);

            // exact in-bin rank; push the kneed smallest keys (keys distinct)
            for (int t = tid; t < C; t += 1024) {
                unsigned long long mk = binkeys[t];
                int r = 0;
                for (int j2 = 0; j2 < C; j2++) r += (binkeys[j2] < mk);
                if (r < kneed) {
                    int c = (int)(mk & 127ULL);
                    int pos = atomicAdd(&bcnt[c], 1);
                    if (pos < MAXB) buckets[c * MAXB + pos] = mk;
                }
            }
            __syncthreads();
        }
    }

    // ================= phase N: per-class NMS (one warp per class) ==================
    {
        unsigned char* wbase = sm + OFF_REGION + wid * 3328;
        float4* bxs = (float4*)wbase;                    // 2048
        float*  ar  = (float*)(wbase + 2048);            // 512
        float*  sv  = (float*)(wbase + 2560);            // 512
        unsigned char* rm = wbase + 3072;                // 128

        for (int c = wid; c < 80; c += 32) {
            unsigned long long* kb = buckets + c * MAXB;
            int cnt = min(bcnt[c], MAXB);
            if (cnt == 0) continue;

            // warp bitonic sort ascending (== score desc, idx asc), in place
            int m = 2; while (m < cnt) m <<= 1;
            for (int i = lane; i < m; i += 32) if (i >= cnt) kb[i] = ~0ULL;
            __syncwarp();
            for (int kk = 2; kk <= m; kk <<= 1)
                for (int jj = kk >> 1; jj > 0; jj >>= 1) {
                    for (int cc = lane; cc < (m >> 1); cc += 32) {
                        int i1 = ((cc & ~(jj - 1)) << 1) | (cc & (jj - 1));
                        int l1 = i1 | jj;
                        bool up = ((i1 & kk) == 0);
                        unsigned long long a2 = kb[i1], d2 = kb[l1];
                        if ((a2 > d2) == up) { kb[i1] = d2; kb[l1] = a2; }
                    }
                    __syncwarp();
                }

            // decode
            for (int i = lane; i < cnt; i += 32) {
                unsigned long long key = kb[i];
                int idx = (int)((key >> 7) & 0x7FFFULL);
                sv[i] = key_score(key);
                rm[i] = 0;
                float4 an = reinterpret_cast<const float4*>(anchors)[idx];
                float cx = (an.x + an.z) * 0.5f, cy = (an.y + an.w) * 0.5f;
                float4 r = reinterpret_cast<const float4*>(reg)[(size_t)b * TOTAL + idx];
                float x1 = fminf(fmaxf(cx - r.x, 0.0f), IMGF);
                float y1 = fminf(fmaxf(cy - r.y, 0.0f), IMGF);
                float x2 = fminf(fmaxf(cx + r.z, 0.0f), IMGF);
                float y2 = fminf(fmaxf(cy + r.w, 0.0f), IMGF);
                bxs[i] = make_float4(x1, y1, x2, y2);
                ar[i] = fmaxf(x2 - x1, 0.0f) * fmaxf(y2 - y1, 0.0f);
            }
            __syncwarp();

            // greedy NMS (masked sort last; suppressed never suppress)
            for (int i = 0; i < cnt; i++) {
                if (sv[i] <= STH) break;
                if (rm[i]) continue;
                float4 bi = bxs[i];
                float ai = ar[i];
                for (int j = i + 1 + lane; j < cnt; j += 32) {
                    float4 bj = bxs[j];
                    float iw = fmaxf(fminf(bi.z, bj.z) - fmaxf(bi.x, bj.x), 0.0f);
                    float ih = fmaxf(fminf(bi.w, bj.w) - fmaxf(bi.y, bj.y), 0.0f);
                    float inter = iw * ih;
                    float iou = inter / fmaxf(ai + ar[j] - inter, 1e-9f);
                    if (iou > NMST) rm[j] = 1;
                }
                __syncwarp();
            }

            // append survivors in sorted order, per-class cap DETS
            // (rank-100+ within a class can't reach the global top-100)
            int wcnt = 0;
            for (int base2 = 0; base2 < cnt; base2 += 32) {
                int i = base2 + lane;
                bool acc = (i < cnt) && (sv[i] > STH) && !rm[i];
                unsigned bal = __ballot_sync(0xFFFFFFFFu, acc);
                int nb = __popc(bal);
                int nTake = min(nb, max(0, DETS - wcnt));
                int pos = 0;
                if (lane == 0 && nTake > 0) pos = atomicAdd(&sh_sur, nTake);
                pos = __shfl_sync(0xFFFFFFFFu, pos, 0);
                int rk = __popc(bal & ((1u << lane) - 1));
                if (acc && rk < nTake && pos + rk < SCAP) survivors[pos + rk] = kb[i];
                wcnt += nb;
            }
        }
    }
    __syncthreads();

    // ================= phase O: top-100 of survivors, decode, write ==================
    {
        unsigned* hist = (unsigned*)(sm + OFF_REGION);                     // reuse
        unsigned long long* cont = (unsigned long long*)(sm + OFF_REGION + BINN * 4);

        int S = min(sh_sur, SCAP);
        int ns = min(DETS, S);

        for (int i = tid; i < BINN; i += 1024) hist[i] = 0;
        if (tid == 0) { sh_cc = 0; sh_Q = 0; }
        __syncthreads();

        for (int i = tid; i < S; i += 1024)
            atomicAdd(&hist[qbin((unsigned)(survivors[i] >> 32))], 1u);
        __syncthreads();

        if (ns > 0) {
            // descending-bin scan: first bin where cum >= ns
            int vv[4], mysum = 0;
#pragma unroll
            for (int j = 0; j < 4; j++) { vv[j] = hist[BINN - 1 - (tid * 4 + j)]; mysum += vv[j]; }
            int inc = mysum;
#pragma unroll
            for (int o = 1; o < 32; o <<= 1) { int t2 = __shfl_up_sync(0xFFFFFFFFu, inc, o); if (lane >= o) inc += t2; }
            if (lane == 31) warpsum[wid] = inc;
            __syncthreads();
            if (tid < 32) {
                int w = warpsum[tid], s = w;
#pragma unroll
                for (int o = 1; o < 32; o <<= 1) { int t2 = __shfl_up_sync(0xFFFFFFFFu, s, o); if (tid >= o) s += t2; }
                warpsum[tid] = s - w;
            }
            __syncthreads();
            int c = warpsum[wid] + inc - mysum;
#pragma unroll
            for (int j = 0; j < 4; j++) {
                if (c < ns && c + vv[j] >= ns) sh_Q = BINN - 1 - (tid * 4 + j);
                c += vv[j];
            }
            __syncthreads();
            int Q = sh_Q;

            // contention = all bins >= Q (superset of the top-ns)
            for (int i = tid; i < S; i += 1024) {
                unsigned long long key = survivors[i];
                if (qbin((unsigned)(key >> 32)) >= Q) {
                    int p = atomicAdd(&sh_cc, 1);
                    if (p < OCAP) cont[p] = key;
                }
            }
            __syncthreads();
            int C = min(sh_cc, OCAP);

            // exact rank within contention == global rank for r < ns
            for (int t = tid; t < C; t += 1024) {
                unsigned long long mk = cont[t];
                int r = 0;
                for (int q2 = 0; q2 < C; q2++) r += (cont[q2] < mk);
                if (r < ns) win[r] = mk;
            }
        }
        __syncthreads();

        // decode + write
        for (int t = tid; t < DETS; t += 1024) {
            float* ob = out + ((size_t)b * DETS + t) * 4;
            if (t >= ns) {
                ob[0] = 0.0f; ob[1] = 0.0f; ob[2] = 0.0f; ob[3] = 0.0f;
                out[BATCH * DETS * 4 + b * DETS + t] = 0.0f;
                out[BATCH * DETS * 5 + b * DETS + t] = -1.0f;
            } else {
                unsigned long long key = win[t];
                int idx = (int)((key >> 7) & 0x7FFFULL);
                float4 an = reinterpret_cast<const float4*>(anchors)[idx];
                float cx = (an.x + an.z) * 0.5f, cy = (an.y + an.w) * 0.5f;
                float4 r = reinterpret_cast<const float4*>(reg)[(size_t)b * TOTAL + idx];
                float x1 = fminf(fmaxf(cx - r.x, 0.0f), IMGF);
                float y1 = fminf(fmaxf(cy - r.y, 0.0f), IMGF);
                float x2 = fminf(fmaxf(cx + r.z, 0.0f), IMGF);
                float y2 = fminf(fmaxf(cy + r.w, 0.0f), IMGF);
                ob[0] = x1; ob[1] = y1; ob[2] = x2; ob[3] = y2;
                out[BATCH * DETS * 4 + b * DETS + t] = key_score(key);
                out[BATCH * DETS * 5 + b * DETS + t] = (float)(key & 127ULL);
            }
        }
    }
}

// ---------------- launch ----------------
extern "C" void kernel_launch(void* const* d_in, const int* in_sizes, int n_in,
                              void* d_out, int out_size) {
    const float* logits  = (const float*)d_in[0];  // (8, 21824, 80)
    const float* reg     = (const float*)d_in[1];  // (8, 21824, 4)
    const float* ctr     = (const float*)d_in[2];  // (8, 21824, 1)
    const float* anchors = (const float*)d_in[3];  // (21824, 4)
    float* out = (float*)d_out;

    cudaFuncSetAttribute(k_batch, cudaFuncAttributeMaxDynamicSharedMemorySize, BATCH_SMEM);

    k_score<<<(BATCH * TOTAL) / 128, 512>>>(logits, ctr);
    k_batch<<<BATCH, 1024, BATCH_SMEM>>>(reg, anchors, out);
}

// round 11
// speedup vs baseline: 1.9242x; 1.9242x over previous
#include <cuda_runtime.h>
#include <math.h>
#include <stdint.h>

#define BATCH 8
#define TOTAL 21824
#define DETS  100
#define IMGF  1024.0f
#define STH   0.2f
#define NMST  0.6f
#define MAXB  128    // per-class bucket capacity (mean ~41, 13-sigma safe)
#define BINN  4096   // quantization bins
#define BCAP  512    // boundary-bin capacity (expected ~16)
#define OCAP  1024   // out contention capacity (expected ~110)
#define SCAP  3328   // compact survivor capacity per batch (max possible 3320)

// ---------------- scratch ----------------
__device__ unsigned long long d_keys[BATCH * TOTAL];
__device__ unsigned long long d_bucket[BATCH * 80 * MAXB];
__device__ int                d_ccnt[BATCH * 80];
__device__ unsigned long long d_sur[BATCH * SCAP];
__device__ int                d_surtot[BATCH];

__device__ __forceinline__ float sigf(float x) { return 1.0f / (1.0f + expf(-x)); }

__device__ __forceinline__ float key_score_hi(unsigned h) {
    unsigned uo = ~h;
    unsigned bits = (uo & 0x80000000u) ? (uo ^ 0x80000000u) : (~uo);
    return __uint_as_float(bits);
}
__device__ __forceinline__ float key_score(unsigned long long key) {
    return key_score_hi((unsigned)(key >> 32));
}
// monotone: higher score -> higher bin; masked (-1) -> bin 0
__device__ __forceinline__ int qbin(unsigned h) {
    float s = key_score_hi(h);
    return (s > 0.0f) ? min(BINN - 1, (int)(s * (float)BINN)) : 0;
}

__device__ __forceinline__ void bucket_push(int b, unsigned long long key) {
    int c = (int)(key & 127ULL);
    int pos = atomicAdd(&d_ccnt[b * 80 + c], 1);
    if (pos < MAXB) d_bucket[(size_t)(b * 80 + c) * MAXB + pos] = key;
}

// ---------------- K1: staged coalesced score + argmax -> 64-bit key ----------------
// key = (~orderable(score))<<32 | idx<<7 | label : ascending == (score desc, idx asc);
// keys globally distinct; matches jax.lax.top_k stable tie order.
__global__ __launch_bounds__(512) void k_score(const float* __restrict__ logits,
                                               const float* __restrict__ ctr) {
    __shared__ float4 s4[128 * 20];  // 40 KB
    int tid = threadIdx.x;
    if (blockIdx.x == 0) {
        for (int i = tid; i < BATCH * 80; i += 512) d_ccnt[i] = 0;
        if (tid < BATCH) d_surtot[tid] = 0;
    }
    const float4* g = reinterpret_cast<const float4*>(logits) + (size_t)blockIdx.x * (128 * 20);
#pragma unroll
    for (int i = 0; i < 5; i++) s4[i * 512 + tid] = __ldcs(&g[i * 512 + tid]);
    __syncthreads();

    int la = tid >> 2;   // local anchor 0..127
    int q  = tid & 3;    // quarter: cols 20q..20q+19
    const float4* rowq = s4 + la * 20 + q * 5;
    float best = -1e30f;
    int bi = 0;
#pragma unroll
    for (int i = 0; i < 5; i++) {  // strict > keeps first-max within lane
        float4 v = rowq[i];
        int cb = q * 20 + i * 4;
        if (v.x > best) { best = v.x; bi = cb + 0; }
        if (v.y > best) { best = v.y; bi = cb + 1; }
        if (v.z > best) { best = v.z; bi = cb + 2; }
        if (v.w > best) { best = v.w; bi = cb + 3; }
    }
#pragma unroll
    for (int o = 2; o >= 1; o >>= 1) {  // tie -> lower column (= first occurrence)
        float ov = __shfl_down_sync(0xFFFFFFFFu, best, o);
        int   oc = __shfl_down_sync(0xFFFFFFFFu, bi, o);
        if (ov > best || (ov == best && oc < bi)) { best = ov; bi = oc; }
    }
    if (q == 0) {
        int ga = blockIdx.x * 128 + la;   // BATCH*TOTAL % 128 == 0
        float s = sqrtf(sigf(best) * sigf(ctr[ga]));
        float sm = (s > STH) ? s : -1.0f;
        unsigned u = __float_as_uint(sm);
        u ^= (u & 0x80000000u) ? 0xFFFFFFFFu : 0x80000000u;
        int i_loc = ga % TOTAL;
        d_keys[ga] = ((unsigned long long)(~u) << 32) |
                     ((unsigned)(i_loc << 7) | (unsigned)bi);
    }
}

// ---------------- K2: per (batch, level) exact top-k via quantized bins --------------
// Sweep 1 (global): stage keys to SMEM + 4096-bin histogram (plain spread atomics).
// Scan: boundary bin Q + kneed. Sweep 2 (SMEM): push bins>Q to class buckets, collect
// boundary bin. Rank: push kneed smallest boundary keys. Exact incl. ties.
#define SEL_SMEM (131072 + BINN * 4 + BCAP * 8)   // hi/lo 128K | hist 16K | binkeys 4K

__global__ __launch_bounds__(1024, 1) void k_select() {
    extern __shared__ unsigned char smraw[];
    const int LOFF[5] = {0, 16384, 20480, 21504, 21760};
    const int LN[5]   = {16384, 4096, 1024, 256, 64};
    const int LK[5]   = {1000, 1000, 1000, 256, 64};

    int b = blockIdx.x / 5, lvl = blockIdx.x % 5;
    int off = LOFF[lvl], n = LN[lvl], k = LK[lvl];
    int tid = threadIdx.x, lane = tid & 31, wid = tid >> 5;
    const unsigned long long* kp = d_keys + b * TOTAL + off;

    if (k >= n) {  // levels 3,4: everything selected
        for (int i = tid; i < n; i += 1024) bucket_push(b, kp[i]);
        return;
    }

    unsigned* hi = (unsigned*)smraw;
    unsigned* lo = hi + n;
    unsigned* hist = (unsigned*)(smraw + 131072);
    unsigned long long* binkeys = (unsigned long long*)(smraw + 131072 + BINN * 4);
    __shared__ int warpsum[32];
    __shared__ int sh_Q, sh_kneed, sh_bc;

    for (int i = tid; i < BINN; i += 1024) hist[i] = 0;
    if (tid == 0) sh_bc = 0;
    __syncthreads();

    // sweep 1: stage + histogram (no warp-sync ops -> load latency pipelines)
    for (int i = tid; i < n; i += 1024) {
        unsigned long long key = kp[i];
        unsigned h = (unsigned)(key >> 32);
        hi[i] = h;
        lo[i] = (unsigned)key;
        atomicAdd(&hist[qbin(h)], 1u);
    }
    __syncthreads();

    // descending-bin cumulative scan (4 bins/thread): boundary bin Q, kneed
    {
        int vv[4], mysum = 0;
#pragma unroll
        for (int j = 0; j < 4; j++) { vv[j] = hist[BINN - 1 - (tid * 4 + j)]; mysum += vv[j]; }
        int inc = mysum;
#pragma unroll
        for (int o = 1; o < 32; o <<= 1) { int t2 = __shfl_up_sync(0xFFFFFFFFu, inc, o); if (lane >= o) inc += t2; }
        if (lane == 31) warpsum[wid] = inc;
        __syncthreads();
        if (tid < 32) {
            int w = warpsum[tid], s = w;
#pragma unroll
            for (int o = 1; o < 32; o <<= 1) { int t2 = __shfl_up_sync(0xFFFFFFFFu, s, o); if (tid >= o) s += t2; }
            warpsum[tid] = s - w;  // exclusive
        }
        __syncthreads();
        int c = warpsum[wid] + inc - mysum;
#pragma unroll
        for (int j = 0; j < 4; j++) {
            if (c < k && c + vv[j] >= k) {
                sh_Q = BINN - 1 - (tid * 4 + j);
                sh_kneed = k - c;
            }
            c += vv[j];
        }
    }
    __syncthreads();
    int Q = sh_Q, kneed = sh_kneed;

    // sweep 2 (SMEM): push bins > Q; collect boundary bin
    for (int i = tid; i < n; i += 1024) {
        unsigned h = hi[i];
        int q = qbin(h);
        if (q > Q) {
            bucket_push(b, ((unsigned long long)h << 32) | lo[i]);
        } else if (q == Q) {
            int p = atomicAdd(&sh_bc, 1);
            if (p < BCAP) binkeys[p] = ((unsigned long long)h << 32) | lo[i];
        }
    }
    __syncthreads();
    int C = min(sh_bc, BCAP);

    // exact in-bin rank; push the kneed smallest boundary keys (keys distinct)
    for (int t = tid; t < C; t += 1024) {
        unsigned long long mk = binkeys[t];
        int r = 0;
        for (int j2 = 0; j2 < C; j2++) r += (binkeys[j2] < mk);
        if (r < kneed) bucket_push(b, mk);
    }
}

// ---------------- K3: one warp per (batch,class): sort bucket, NMS, compact append ----
__global__ __launch_bounds__(32) void k_nms(const float* __restrict__ reg,
                                            const float* __restrict__ anchors) {
    int bc = blockIdx.x, b = bc / 80;
    __shared__ unsigned long long kb[MAXB];
    __shared__ float4 bxs[MAXB];
    __shared__ float  ar[MAXB], sv[MAXB];
    __shared__ unsigned char rm[MAXB];
    int lane = threadIdx.x;

    int cnt = min(d_ccnt[bc], MAXB);
    if (cnt == 0) return;
    for (int i = lane; i < cnt; i += 32)
        kb[i] = d_bucket[(size_t)bc * MAXB + i];
    __syncwarp();

    // warp bitonic sort ascending (== score desc, idx asc)
    int m = 2; while (m < cnt) m <<= 1;
    for (int i = lane; i < m; i += 32) if (i >= cnt) kb[i] = ~0ULL;
    __syncwarp();
    for (int kk = 2; kk <= m; kk <<= 1)
        for (int jj = kk >> 1; jj > 0; jj >>= 1) {
            for (int cc = lane; cc < (m >> 1); cc += 32) {
                int i1 = ((cc & ~(jj - 1)) << 1) | (cc & (jj - 1));
                int l1 = i1 | jj;
                bool up = ((i1 & kk) == 0);
                unsigned long long a2 = kb[i1], d2 = kb[l1];
                if ((a2 > d2) == up) { kb[i1] = d2; kb[l1] = a2; }
            }
            __syncwarp();
        }

    // decode
    for (int i = lane; i < cnt; i += 32) {
        unsigned long long key = kb[i];
        int idx = (int)((key >> 7) & 0x7FFFULL);
        sv[i] = key_score(key);
        rm[i] = 0;
        float4 an = reinterpret_cast<const float4*>(anchors)[idx];
        float cx = (an.x + an.z) * 0.5f, cy = (an.y + an.w) * 0.5f;
        float4 r = reinterpret_cast<const float4*>(reg)[(size_t)b * TOTAL + idx];
        float x1 = fminf(fmaxf(cx - r.x, 0.0f), IMGF);
        float y1 = fminf(fmaxf(cy - r.y, 0.0f), IMGF);
        float x2 = fminf(fmaxf(cx + r.z, 0.0f), IMGF);
        float y2 = fminf(fmaxf(cy + r.w, 0.0f), IMGF);
        bxs[i] = make_float4(x1, y1, x2, y2);
        ar[i] = fmaxf(x2 - x1, 0.0f) * fmaxf(y2 - y1, 0.0f);
    }
    __syncwarp();

    // greedy NMS (masked sort last; suppressed never suppress)
    for (int i = 0; i < cnt; i++) {
        if (sv[i] <= STH) break;
        if (rm[i]) continue;
        float4 bi = bxs[i];
        float ai = ar[i];
        for (int j = i + 1 + lane; j < cnt; j += 32) {
            float4 bj = bxs[j];
            float iw = fmaxf(fminf(bi.z, bj.z) - fmaxf(bi.x, bj.x), 0.0f);
            float ih = fmaxf(fminf(bi.w, bj.w) - fmaxf(bi.y, bj.y), 0.0f);
            float inter = iw * ih;
            float iou = inter / fmaxf(ai + ar[j] - inter, 1e-9f);
            if (iou > NMST) rm[j] = 1;
        }
        __syncwarp();
    }

    // append survivors (per-class cap DETS; rank-100+ of a class can't reach top-100)
    int wcnt = 0;
    for (int base = 0; base < cnt; base += 32) {
        int i = base + lane;
        bool acc = (i < cnt) && (sv[i] > STH) && !rm[i];
        unsigned bal = __ballot_sync(0xFFFFFFFFu, acc);
        int nb = __popc(bal);
        int nTake = min(nb, max(0, DETS - wcnt));
        int pos = 0;
        if (lane == 0 && nTake > 0) pos = atomicAdd(&d_surtot[b], nTake);
        pos = __shfl_sync(0xFFFFFFFFu, pos, 0);
        int rk = __popc(bal & ((1u << lane) - 1));
        if (acc && rk < nTake && pos + rk < SCAP) d_sur[(size_t)b * SCAP + pos + rk] = kb[i];
        wcnt += nb;
    }
}

// ---------------- K4: per-batch top-100 of compact survivors ---------------------------
__global__ __launch_bounds__(1024, 1) void k_out(const float* __restrict__ reg,
                                                 const float* __restrict__ anchors,
                                                 float* __restrict__ out) {
    extern __shared__ unsigned char smraw[];
    unsigned long long* skey = (unsigned long long*)smraw;          // SCAP*8 = 26624
    unsigned* hist = (unsigned*)(smraw + SCAP * 8);                  // 16384
    unsigned long long* cont = (unsigned long long*)(smraw + SCAP * 8 + BINN * 4);  // 8192
    __shared__ unsigned long long win[DETS];
    __shared__ int warpsum[32];
    __shared__ int sh_cc, sh_Q;

    int b = blockIdx.x, tid = threadIdx.x, lane = tid & 31, wid = tid >> 5;

    int S = min(d_surtot[b], SCAP);
    int ns = min(DETS, S);

    for (int i = tid; i < BINN; i += 1024) hist[i] = 0;
    if (tid == 0) { sh_cc = 0; sh_Q = 0; }
    __syncthreads();

    // one coalesced sweep: stage + histogram
    for (int i = tid; i < S; i += 1024) {
        unsigned long long key = d_sur[(size_t)b * SCAP + i];
        skey[i] = key;
        atomicAdd(&hist[qbin((unsigned)(key >> 32))], 1u);
    }
    __syncthreads();

    if (ns > 0) {
        // descending-bin scan: first bin where cum >= ns
        int vv[4], mysum = 0;
#pragma unroll
        for (int j = 0; j < 4; j++) { vv[j] = hist[BINN - 1 - (tid * 4 + j)]; mysum += vv[j]; }
        int inc = mysum;
#pragma unroll
        for (int o = 1; o < 32; o <<= 1) { int t2 = __shfl_up_sync(0xFFFFFFFFu, inc, o); if (lane >= o) inc += t2; }
        if (lane == 31) warpsum[wid] = inc;
        __syncthreads();
        if (tid < 32) {
            int w = warpsum[tid], s = w;
#pragma unroll
            for (int o = 1; o < 32; o <<= 1) { int t2 = __shfl_up_sync(0xFFFFFFFFu, s, o); if (tid >= o) s += t2; }
            warpsum[tid] = s - w;
        }
        __syncthreads();
        int c = warpsum[wid] + inc - mysum;
#pragma unroll
        for (int j = 0; j < 4; j++) {
            if (c < ns && c + vv[j] >= ns) sh_Q = BINN - 1 - (tid * 4 + j);
            c += vv[j];
        }
        __syncthreads();
        int Q = sh_Q;

        // contention = all bins >= Q (superset of the top-ns)
        for (int i = tid; i < S; i += 1024) {
            unsigned long long key = skey[i];
            if (qbin((unsigned)(key >> 32)) >= Q) {
                int p = atomicAdd(&sh_cc, 1);
                if (p < OCAP) cont[p] = key;
            }
        }
        __syncthreads();
        int C = min(sh_cc, OCAP);

        // exact rank within contention == global rank for r < ns
        for (int t = tid; t < C; t += 1024) {
            unsigned long long mk = cont[t];
            int r = 0;
            for (int q2 = 0; q2 < C; q2++) r += (cont[q2] < mk);
            if (r < ns) win[r] = mk;
        }
    }
    __syncthreads();

    // decode + write
    for (int t = tid; t < DETS; t += 1024) {
        float* ob = out + ((size_t)b * DETS + t) * 4;
        if (t >= ns) {
            ob[0] = 0.0f; ob[1] = 0.0f; ob[2] = 0.0f; ob[3] = 0.0f;
            out[BATCH * DETS * 4 + b * DETS + t] = 0.0f;
            out[BATCH * DETS * 5 + b * DETS + t] = -1.0f;
        } else {
            unsigned long long key = win[t];
            int idx = (int)((key >> 7) & 0x7FFFULL);
            float4 an = reinterpret_cast<const float4*>(anchors)[idx];
            float cx = (an.x + an.z) * 0.5f, cy = (an.y + an.w) * 0.5f;
            float4 r = reinterpret_cast<const float4*>(reg)[(size_t)b * TOTAL + idx];
            float x1 = fminf(fmaxf(cx - r.x, 0.0f), IMGF);
            float y1 = fminf(fmaxf(cy - r.y, 0.0f), IMGF);
            float x2 = fminf(fmaxf(cx + r.z, 0.0f), IMGF);
            float y2 = fminf(fmaxf(cy + r.w, 0.0f), IMGF);
            ob[0] = x1; ob[1] = y1; ob[2] = x2; ob[3] = y2;
            out[BATCH * DETS * 4 + b * DETS + t] = key_score(key);
            out[BATCH * DETS * 5 + b * DETS + t] = (float)(key & 127ULL);
        }
    }
}

// ---------------- launch ----------------
extern "C" void kernel_launch(void* const* d_in, const int* in_sizes, int n_in,
                              void* d_out, int out_size) {
    const float* logits  = (const float*)d_in[0];  // (8, 21824, 80)
    const float* reg     = (const float*)d_in[1];  // (8, 21824, 4)
    const float* ctr     = (const float*)d_in[2];  // (8, 21824, 1)
    const float* anchors = (const float*)d_in[3];  // (21824, 4)
    float* out = (float*)d_out;

    cudaFuncSetAttribute(k_select, cudaFuncAttributeMaxDynamicSharedMemorySize, SEL_SMEM);
    cudaFuncSetAttribute(k_out, cudaFuncAttributeMaxDynamicSharedMemorySize,
                         SCAP * 8 + BINN * 4 + OCAP * 8);

    k_score<<<(BATCH * TOTAL) / 128, 512>>>(logits, ctr);
    k_select<<<BATCH * 5, 1024, SEL_SMEM>>>();
    k_nms<<<BATCH * 80, 32>>>(reg, anchors);
    k_out<<<BATCH, 1024, SCAP * 8 + BINN * 4 + OCAP * 8>>>(reg, anchors, out);
}